// round 5
// baseline (speedup 1.0000x reference)
#include <cuda_runtime.h>
#include <math.h>

#define IMG 256
#define NVERT 642
#define NFACE 1280
#define NBATCH 2
#define SHARP (2.0f * (float)IMG)
#define GCHUNK 64    // faces whose coefficients are computed per barrier round
#define SUB 32       // pixel-loop subpass size (saturation check between subpasses)
#define TAU 0.04f    // sigmoid(SHARP*TAU) >= 1 - 1.3e-9

// Fully fused, gather-on-demand. Grid (IMG*IMG/512, NBATCH).
// Block: 256 threads = 2 rows x 128 threads x 2 px.
__global__ __launch_bounds__(256) void fused_kernel(const float* __restrict__ verts,
                                                    const int* __restrict__ faces,
                                                    const float* __restrict__ cams,
                                                    float* __restrict__ out) {
    const int b    = blockIdx.y;
    const int tile = blockIdx.x;
    const int t    = threadIdx.x;

    __shared__ __align__(16) float4 sf0[GCHUNK];   // A1,B1,C1,A2
    __shared__ __align__(16) float4 sf1[GCHUNK];   // B2,C2,A3,B3
    __shared__ __align__(8)  float2 sf2[GCHUNK];   // C3, orient

    // ---- camera constants (redundant per thread; broadcast loads)
    const float* cam = cams + b * 7;
    float s  = cam[0];
    float tcx = cam[1];
    float tcy = cam[2];
    float qw = cam[3], qx = cam[4], qy = cam[5], qz = cam[6];
    float qn = rsqrtf(qw * qw + qx * qx + qy * qy + qz * qz);
    qw *= qn; qx *= qn; qy *= qn; qz *= qn;
    const float r00 = 1.f - 2.f * (qy * qy + qz * qz);
    const float r01 = 2.f * (qx * qy - qw * qz);
    const float r02 = 2.f * (qx * qz + qw * qy);
    const float r10 = 2.f * (qx * qy + qw * qz);
    const float r11 = 1.f - 2.f * (qx * qx + qz * qz);
    const float r12 = 2.f * (qy * qz - qw * qx);

    const float* vbase = verts + (size_t)b * NVERT * 3;
    const int*   fbase = faces + (size_t)b * NFACE * 3;

    // ---- per-pixel setup: 2 px/thread
    const int row = tile * 2 + (t >> 7);
    const int xs  = (t & 127) * 2;
    const float inv = 2.0f / (float)IMG;
    const float py  = ((float)row + 0.5f) * inv - 1.0f;
    const float px0 = ((float)(xs)     + 0.5f) * inv - 1.0f;
    const float px1 = ((float)(xs + 1) + 0.5f) * inv - 1.0f;
    float acc0 = -3.402823466e+38f;
    float acc1 = -3.402823466e+38f;

    bool done = false;
    for (int c = 0; c < NFACE; c += GCHUNK) {
        // ---- coefficients for 64 faces: 192 edge-tasks, gathered from gmem
        if (t < 3 * GCHUNK) {
            const int f = t / 3;
            const int e = t - 3 * f;
            const int* fi = fbase + (size_t)(c + f) * 3;
            const int ia = fi[e];
            const int ib = fi[(e == 2) ? 0 : e + 1];

            const float* va = vbase + (size_t)ia * 3;
            float aX = va[0], aY = va[1], aZ = va[2];
            const float* vb = vbase + (size_t)ib * 3;
            float bX = vb[0], bY = vb[1], bZ = vb[2];

            float ax =  s * (r00 * aX + r01 * aY + r02 * aZ) + tcx;
            float ay = -(s * (r10 * aX + r11 * aY + r12 * aZ) + tcy);
            float bx =  s * (r00 * bX + r01 * bY + r02 * bZ) + tcx;
            float by = -(s * (r10 * bX + r11 * bY + r12 * bZ) + tcy);

            float ex = bx - ax;
            float ey = by - ay;
            float il = rsqrtf(ex * ex + ey * ey + 1e-12f);
            float exn = ex * il;
            float eyn = ey * il;
            float A = -eyn;
            float B = exn;
            float C = eyn * ax - exn * ay;

            if (e == 0) {
                sf0[f].x = A; sf0[f].y = B; sf0[f].z = C;
                const int i2 = fi[2];
                const float* vc = vbase + (size_t)i2 * 3;
                float cX = vc[0], cY = vc[1], cZ = vc[2];
                float x2 =  s * (r00 * cX + r01 * cY + r02 * cZ) + tcx;
                float y2 = -(s * (r10 * cX + r11 * cY + r12 * cZ) + tcy);
                float area2 = ex * (y2 - ay) - ey * (x2 - ax);
                sf2[f].y = (area2 > 0.f) ? 1.f : ((area2 < 0.f) ? -1.f : 0.f);
            } else if (e == 1) {
                sf0[f].w = A; sf1[f].x = B; sf1[f].y = C;
            } else {
                sf1[f].z = A; sf1[f].w = B; sf2[f].x = C;
            }
        }
        __syncthreads();

        if (!done) {
            #pragma unroll 1
            for (int sub = 0; sub < GCHUNK && !done; sub += SUB) {
                #pragma unroll 4
                for (int f = sub; f < sub + SUB; ++f) {
                    float4 e0 = sf0[f];
                    float4 e1 = sf1[f];
                    float2 e2 = sf2[f];
                    float t1 = fmaf(e0.y, py, e0.z);
                    float t2 = fmaf(e1.x, py, e1.y);
                    float t3 = fmaf(e1.w, py, e2.x);
                    float o  = e2.y;

                    float d1 = fmaf(e0.x, px0, t1);
                    float d2 = fmaf(e0.w, px0, t2);
                    float d3 = fmaf(e1.z, px0, t3);
                    acc0 = fmaxf(acc0, o * fminf(fminf(d1, d2), d3));

                    d1 = fmaf(e0.x, px1, t1);
                    d2 = fmaf(e0.w, px1, t2);
                    d3 = fmaf(e1.z, px1, t3);
                    acc1 = fmaxf(acc1, o * fminf(fminf(d1, d2), d3));
                }
                // warp-uniform saturation vote (cheap; no barrier)
                float m = fminf(acc0, acc1);
                done = (__all_sync(0xffffffffu, m >= TAU) != 0);
            }
        }
        // block-collective exit; also protects sf* reuse next round
        if (__syncthreads_and(done ? 1 : 0)) break;
    }

    float2 res;
    res.x = 1.0f / (1.0f + __expf(-SHARP * acc0));
    res.y = 1.0f / (1.0f + __expf(-SHARP * acc1));
    float2* op = (float2*)(out + (size_t)b * IMG * IMG + (size_t)row * IMG + xs);
    *op = res;
}

extern "C" void kernel_launch(void* const* d_in, const int* in_sizes, int n_in,
                              void* d_out, int out_size) {
    const float* verts = (const float*)d_in[0];  // [2, 642, 3] f32
    const int*   faces = (const int*)d_in[1];    // [2, 1280, 3] i32
    const float* cams  = (const float*)d_in[2];  // [2, 7] f32
    float* out = (float*)d_out;                  // [2, 256, 256] f32

    fused_kernel<<<dim3(IMG * IMG / 512, NBATCH), 256>>>(verts, faces, cams, out);
}

// round 7
// speedup vs baseline: 1.1570x; 1.1570x over previous
#include <cuda_runtime.h>
#include <math.h>

#define IMG 256
#define NVERT 642
#define NFACE 1280
#define NBATCH 2
#define SHARP (2.0f * (float)IMG)
#define TAU 0.04f    // sigmoid(SHARP*TAU) >= 1 - 1.3e-9: later faces can't change output

// Per-warp autonomous renderer. Grid (IMG*IMG/512, NBATCH); block 256 = 8 warps.
// Warp covers 64 contiguous px of one row (2 px/lane). Each round: 32 lanes
// compute coefficients for 32 faces (one each), __syncwarp, pixel loop with a
// saturation vote every 8 faces. NO block-level barriers.
__global__ __launch_bounds__(256) void fused_kernel(const float* __restrict__ verts,
                                                    const int* __restrict__ faces,
                                                    const float* __restrict__ cams,
                                                    float* __restrict__ out) {
    const int b    = blockIdx.y;
    const int tile = blockIdx.x;
    const int t    = threadIdx.x;
    const int w    = t >> 5;          // warp id in block (0..7)
    const int lane = t & 31;

    // Per-warp coefficient slab: [warp][face][2] float4 = (A1,A2,A3,t1),(t2,t3,o,pad)
    __shared__ __align__(16) float4 sw[8][32][2];

    // ---- camera constants (broadcast loads; independent of face loads below)
    const float* cam = cams + b * 7;
    float s   = cam[0];
    float tcx = cam[1];
    float tcy = cam[2];
    float qw = cam[3], qx = cam[4], qy = cam[5], qz = cam[6];
    float qn = rsqrtf(qw * qw + qx * qx + qy * qy + qz * qz);
    qw *= qn; qx *= qn; qy *= qn; qz *= qn;
    const float r00 = 1.f - 2.f * (qy * qy + qz * qz);
    const float r01 = 2.f * (qx * qy - qw * qz);
    const float r02 = 2.f * (qx * qz + qw * qy);
    const float r10 = 2.f * (qx * qy + qw * qz);
    const float r11 = 1.f - 2.f * (qx * qx + qz * qz);
    const float r12 = 2.f * (qy * qz - qw * qx);

    const float* vbase = verts + (size_t)b * NVERT * 3;
    const int*   fbase = faces + (size_t)b * NFACE * 3;

    // ---- pixel mapping: row = tile*2 + (warp>=4); warp covers 64 px, 2/lane
    const int row = tile * 2 + (w >> 2);
    const int xs  = ((w & 3) * 32 + lane) * 2;
    const float inv = 2.0f / (float)IMG;
    const float py  = ((float)row + 0.5f) * inv - 1.0f;    // warp-uniform
    const float px0 = ((float)(xs)     + 0.5f) * inv - 1.0f;
    const float px1 = ((float)(xs + 1) + 0.5f) * inv - 1.0f;
    float acc0 = -3.402823466e+38f;
    float acc1 = -3.402823466e+38f;

    bool done = false;
    for (int c = 0; c < NFACE && !done; c += 32) {
        // ---- this lane computes full coefficients for face (c + lane)
        {
            const int* fi = fbase + (size_t)(c + lane) * 3;
            const int i0 = fi[0];
            const int i1 = fi[1];
            const int i2 = fi[2];

            const float* v0 = vbase + (size_t)i0 * 3;
            const float* v1 = vbase + (size_t)i1 * 3;
            const float* v2 = vbase + (size_t)i2 * 3;
            float aX = v0[0], aY = v0[1], aZ = v0[2];
            float bX = v1[0], bY = v1[1], bZ = v1[2];
            float cX = v2[0], cY = v2[1], cZ = v2[2];

            float x0 =  s * (r00 * aX + r01 * aY + r02 * aZ) + tcx;
            float y0 = -(s * (r10 * aX + r11 * aY + r12 * aZ) + tcy);
            float x1 =  s * (r00 * bX + r01 * bY + r02 * bZ) + tcx;
            float y1 = -(s * (r10 * bX + r11 * bY + r12 * bZ) + tcy);
            float x2 =  s * (r00 * cX + r01 * cY + r02 * cZ) + tcx;
            float y2 = -(s * (r10 * cX + r11 * cY + r12 * cZ) + tcy);

            // edge 1: v0->v1, edge 2: v1->v2, edge 3: v2->v0
            float e1x = x1 - x0, e1y = y1 - y0;
            float e2x = x2 - x1, e2y = y2 - y1;
            float e3x = x0 - x2, e3y = y0 - y2;
            float il1 = rsqrtf(e1x * e1x + e1y * e1y + 1e-12f);
            float il2 = rsqrtf(e2x * e2x + e2y * e2y + 1e-12f);
            float il3 = rsqrtf(e3x * e3x + e3y * e3y + 1e-12f);
            float ex1 = e1x * il1, ey1 = e1y * il1;
            float ex2 = e2x * il2, ey2 = e2y * il2;
            float ex3 = e3x * il3, ey3 = e3y * il3;

            float A1 = -ey1, t1 = fmaf(ex1, py, ey1 * x0 - ex1 * y0);
            float A2 = -ey2, t2 = fmaf(ex2, py, ey2 * x1 - ex2 * y1);
            float A3 = -ey3, t3 = fmaf(ex3, py, ey3 * x2 - ex3 * y2);

            float area2 = e1x * (y2 - y0) - e1y * (x2 - x0);
            float o = (area2 > 0.f) ? 1.f : ((area2 < 0.f) ? -1.f : 0.f);

            sw[w][lane][0] = make_float4(A1, A2, A3, t1);
            sw[w][lane][1] = make_float4(t2, t3, o, 0.f);
        }
        __syncwarp();

        // ---- pixel loop over this round's 32 faces; vote every 8
        #pragma unroll 1
        for (int g = 0; g < 32 && !done; g += 8) {
            #pragma unroll
            for (int f = g; f < g + 8; ++f) {
                float4 c0 = sw[w][f][0];
                float4 c1 = sw[w][f][1];
                float o = c1.z;

                float d1 = fmaf(c0.x, px0, c0.w);
                float d2 = fmaf(c0.y, px0, c1.x);
                float d3 = fmaf(c0.z, px0, c1.y);
                acc0 = fmaxf(acc0, o * fminf(fminf(d1, d2), d3));

                d1 = fmaf(c0.x, px1, c0.w);
                d2 = fmaf(c0.y, px1, c1.x);
                d3 = fmaf(c0.z, px1, c1.y);
                acc1 = fmaxf(acc1, o * fminf(fminf(d1, d2), d3));
            }
            float m = fminf(acc0, acc1);
            done = (__all_sync(0xffffffffu, m >= TAU) != 0);
        }
        __syncwarp();   // protect sw[w] reuse next round
    }

    float2 res;
    res.x = 1.0f / (1.0f + __expf(-SHARP * acc0));
    res.y = 1.0f / (1.0f + __expf(-SHARP * acc1));
    float2* op = (float2*)(out + (size_t)b * IMG * IMG + (size_t)row * IMG + xs);
    *op = res;
}

extern "C" void kernel_launch(void* const* d_in, const int* in_sizes, int n_in,
                              void* d_out, int out_size) {
    const float* verts = (const float*)d_in[0];  // [2, 642, 3] f32
    const int*   faces = (const int*)d_in[1];    // [2, 1280, 3] i32
    const float* cams  = (const float*)d_in[2];  // [2, 7] f32
    float* out = (float*)d_out;                  // [2, 256, 256] f32

    fused_kernel<<<dim3(IMG * IMG / 512, NBATCH), 256>>>(verts, faces, cams, out);
}

// round 10
// speedup vs baseline: 1.2727x; 1.1000x over previous
#include <cuda_runtime.h>
#include <math.h>

#define IMG 256
#define NVERT 642
#define NFACE 1280
#define NBATCH 2
#define SHARP (2.0f * (float)IMG)
#define TAU 0.04f    // sigmoid(SHARP*TAU) >= 1 - 1.3e-9: later faces can't change output

// Per-warp autonomous renderer, one CTA per SM.
// Block 512 = 16 warps; block covers 4 rows x 256 px = 1024 px.
// Grid (IMG*IMG/1024, NBATCH) = (64, 2) = 128 CTAs (<=148 SMs -> single wave).
// Warp covers 64 px of row tile*4 + (w>>2), 2 px/lane.
// Each round: 32 lanes compute coefficients for 32 faces (one each), __syncwarp,
// pixel loop with a saturation vote every 8 faces. NO block-level barriers.
__global__ __launch_bounds__(512) void fused_kernel(const float* __restrict__ verts,
                                                    const int* __restrict__ faces,
                                                    const float* __restrict__ cams,
                                                    float* __restrict__ out) {
    const int b    = blockIdx.y;
    const int tile = blockIdx.x;
    const int t    = threadIdx.x;
    const int w    = t >> 5;          // warp id in block (0..15)
    const int lane = t & 31;

    // Per-warp coefficient slab: [warp][face][2] float4 = (A1,A2,A3,t1),(t2,t3,o,pad)
    __shared__ __align__(16) float4 sw[16][32][2];

    // ---- camera constants (broadcast loads; independent of face loads below)
    const float* cam = cams + b * 7;
    float s   = cam[0];
    float tcx = cam[1];
    float tcy = cam[2];
    float qw = cam[3], qx = cam[4], qy = cam[5], qz = cam[6];
    float qn = rsqrtf(qw * qw + qx * qx + qy * qy + qz * qz);
    qw *= qn; qx *= qn; qy *= qn; qz *= qn;
    const float r00 = 1.f - 2.f * (qy * qy + qz * qz);
    const float r01 = 2.f * (qx * qy - qw * qz);
    const float r02 = 2.f * (qx * qz + qw * qy);
    const float r10 = 2.f * (qx * qy + qw * qz);
    const float r11 = 1.f - 2.f * (qx * qx + qz * qz);
    const float r12 = 2.f * (qy * qz - qw * qx);

    const float* vbase = verts + (size_t)b * NVERT * 3;
    const int*   fbase = faces + (size_t)b * NFACE * 3;

    // ---- pixel mapping: 4 rows per tile; warp covers 64 px of one row
    const int row = tile * 4 + (w >> 2);
    const int xs  = ((w & 3) * 32 + lane) * 2;
    const float inv = 2.0f / (float)IMG;
    const float py  = ((float)row + 0.5f) * inv - 1.0f;    // warp-uniform
    const float px0 = ((float)(xs)     + 0.5f) * inv - 1.0f;
    const float px1 = ((float)(xs + 1) + 0.5f) * inv - 1.0f;
    float acc0 = -3.402823466e+38f;
    float acc1 = -3.402823466e+38f;

    bool done = false;
    for (int c = 0; c < NFACE && !done; c += 32) {
        // ---- this lane computes full coefficients for face (c + lane)
        {
            const int* fi = fbase + (size_t)(c + lane) * 3;
            const int i0 = fi[0];
            const int i1 = fi[1];
            const int i2 = fi[2];

            const float* v0 = vbase + (size_t)i0 * 3;
            const float* v1 = vbase + (size_t)i1 * 3;
            const float* v2 = vbase + (size_t)i2 * 3;
            float aX = v0[0], aY = v0[1], aZ = v0[2];
            float bX = v1[0], bY = v1[1], bZ = v1[2];
            float cX = v2[0], cY = v2[1], cZ = v2[2];

            float x0 =  s * (r00 * aX + r01 * aY + r02 * aZ) + tcx;
            float y0 = -(s * (r10 * aX + r11 * aY + r12 * aZ) + tcy);
            float x1 =  s * (r00 * bX + r01 * bY + r02 * bZ) + tcx;
            float y1 = -(s * (r10 * bX + r11 * bY + r12 * bZ) + tcy);
            float x2 =  s * (r00 * cX + r01 * cY + r02 * cZ) + tcx;
            float y2 = -(s * (r10 * cX + r11 * cY + r12 * cZ) + tcy);

            // edge 1: v0->v1, edge 2: v1->v2, edge 3: v2->v0
            float e1x = x1 - x0, e1y = y1 - y0;
            float e2x = x2 - x1, e2y = y2 - y1;
            float e3x = x0 - x2, e3y = y0 - y2;
            float il1 = rsqrtf(e1x * e1x + e1y * e1y + 1e-12f);
            float il2 = rsqrtf(e2x * e2x + e2y * e2y + 1e-12f);
            float il3 = rsqrtf(e3x * e3x + e3y * e3y + 1e-12f);
            float ex1 = e1x * il1, ey1 = e1y * il1;
            float ex2 = e2x * il2, ey2 = e2y * il2;
            float ex3 = e3x * il3, ey3 = e3y * il3;

            float A1 = -ey1, t1 = fmaf(ex1, py, ey1 * x0 - ex1 * y0);
            float A2 = -ey2, t2 = fmaf(ex2, py, ey2 * x1 - ex2 * y1);
            float A3 = -ey3, t3 = fmaf(ex3, py, ey3 * x2 - ex3 * y2);

            float area2 = e1x * (y2 - y0) - e1y * (x2 - x0);
            float o = (area2 > 0.f) ? 1.f : ((area2 < 0.f) ? -1.f : 0.f);

            sw[w][lane][0] = make_float4(A1, A2, A3, t1);
            sw[w][lane][1] = make_float4(t2, t3, o, 0.f);
        }
        __syncwarp();

        // ---- pixel loop over this round's 32 faces; vote every 8
        #pragma unroll 1
        for (int g = 0; g < 32 && !done; g += 8) {
            #pragma unroll
            for (int f = g; f < g + 8; ++f) {
                float4 c0 = sw[w][f][0];
                float4 c1 = sw[w][f][1];
                float o = c1.z;

                float d1 = fmaf(c0.x, px0, c0.w);
                float d2 = fmaf(c0.y, px0, c1.x);
                float d3 = fmaf(c0.z, px0, c1.y);
                acc0 = fmaxf(acc0, o * fminf(fminf(d1, d2), d3));

                d1 = fmaf(c0.x, px1, c0.w);
                d2 = fmaf(c0.y, px1, c1.x);
                d3 = fmaf(c0.z, px1, c1.y);
                acc1 = fmaxf(acc1, o * fminf(fminf(d1, d2), d3));
            }
            float m = fminf(acc0, acc1);
            done = (__all_sync(0xffffffffu, m >= TAU) != 0);
        }
        __syncwarp();   // protect sw[w] reuse next round
    }

    float2 res;
    res.x = 1.0f / (1.0f + __expf(-SHARP * acc0));
    res.y = 1.0f / (1.0f + __expf(-SHARP * acc1));
    float2* op = (float2*)(out + (size_t)b * IMG * IMG + (size_t)row * IMG + xs);
    *op = res;
}

extern "C" void kernel_launch(void* const* d_in, const int* in_sizes, int n_in,
                              void* d_out, int out_size) {
    const float* verts = (const float*)d_in[0];  // [2, 642, 3] f32
    const int*   faces = (const int*)d_in[1];    // [2, 1280, 3] i32
    const float* cams  = (const float*)d_in[2];  // [2, 7] f32
    float* out = (float*)d_out;                  // [2, 256, 256] f32

    // Block covers 1024 px -> grid.x = IMG*IMG/1024 = 64; 128 CTAs total.
    fused_kernel<<<dim3(IMG * IMG / 1024, NBATCH), 512>>>(verts, faces, cams, out);
}